// round 5
// baseline (speedup 1.0000x reference)
#include <cuda_runtime.h>
#include <math.h>

#define E_TOTAL 160000
#define NN 10000
#define TILE 64
#define NT 512
#define ASTR 333
#define EPS 1e-8f

// ---- dynamic smem layout (float offsets) ----
#define OFF_A     0                    // 64 x 333         = 21312
#define OFF_VP    21312                // 64 x 108 (v_pre) =  6912 ; reused: VO1 (3072) + VH2 (3072)
#define OFF_VO1   (OFF_VP)
#define OFF_VH2   (OFF_VP + 3072)
#define OFF_VH    28224                // 64 x 108 (v_hid1)=  6912
#define OFF_S2    35136                // 64 x 128 silu2   =  8192
#define OFF_BS    43328                // 2 x (16x128) B double buffer = 4096 (16B aligned)
#define OFF_F     47424                // 64 x 9 frames    =   576
#define OFF_VF    48000                // 64 x 9 vframes   =   576
#define OFF_GATE  48576                // 64 x 16          =  1024
#define OFF_ATTN  49600                // 64
#define OFF_IDX   49664                // 128 ints (rows, cols)
#define OFF_W     49792
// weight sub-offsets within OFF_W
#define W_DOWN1 0
#define W_DF1   1296
#define W_UP1   1404
#define W_G1    1980
#define W_DOWN2 4028
#define W_DF2   4284
#define W_UP2   4332
#define W_G2    4588
#define W_ATT   6636
#define W_BSO1  6764
#define W_BSO2  6892
#define W_BG1   7020
#define W_BG2   7036
#define W_ATTB  7052
#define W_TOTAL 7053
#define SMEM_FLOATS (OFF_W + W_TOTAL)   // 56845 floats = 227380 B < 232448 B limit

// normalized edge indices (handles int32-vs-int64 metadata ambiguity)
__device__ int g_idx[2 * E_TOTAL];

__device__ __forceinline__ float sigm(float x) { return 1.0f / (1.0f + __expf(-x)); }
__device__ __forceinline__ float silu(float x) { return x * sigm(x); }

__device__ __forceinline__ void copyw(float* dst, const float* __restrict__ src, int n, int tid) {
    for (int i = tid; i < n; i += NT) dst[i] = src[i];
}

// Normalize edge_index to int32 regardless of source width.
__global__ void convert_idx_kernel(const int* __restrict__ raw) {
    int any = 0;
    #pragma unroll
    for (int i = 1; i < 64; i += 2) any |= raw[i];
    const bool is64 = (any == 0);
    int i = blockIdx.x * blockDim.x + threadIdx.x;
    if (i < 2 * E_TOTAL) g_idx[i] = is64 ? raw[2 * i] : raw[i];
}

// GEMM: C[2][8] += A_tile[64 x K] @ W[K x 128]. A in smem (stride ASTR),
// W streamed through double-buffered Bs (2 x 16 x 128) with register prefetch.
// ONE __syncthreads per 16-k slice: the barrier of iteration i+1 already orders
// every thread's compute on buffer b (iteration i) before any overwrite of b
// at iteration i+2.
__device__ __forceinline__ void gemm_tile(const float* __restrict__ W, int K,
                                          const float* A, float* Bs,
                                          float C[2][8], int ty, int tx, int tid) {
    float4 pre;
    {
        int kb = min(16, K);
        if (tid < kb * 32) pre = ((const float4*)W)[tid];
    }
    int buf = 0;
    for (int k0 = 0; k0 < K; k0 += 16) {
        const int kb = min(16, K - k0);
        if (tid < kb * 32) ((float4*)(Bs + buf * 2048))[tid] = pre;
        __syncthreads();
        // prefetch next slice while computing this one
        const int k1 = k0 + 16;
        if (k1 < K) {
            int kb1 = min(16, K - k1);
            if (tid < kb1 * 32) pre = ((const float4*)(W + (size_t)k1 * 128))[tid];
        }
        const float* Bb  = Bs + buf * 2048;
        const float* Ar0 = A + (ty * 2 + 0) * ASTR + k0;
        const float* Ar1 = A + (ty * 2 + 1) * ASTR + k0;
        #pragma unroll 4
        for (int kk = 0; kk < kb; ++kk) {
            float a0 = Ar0[kk], a1 = Ar1[kk];
            const float4 p0 = *(const float4*)(Bb + kk * 128 + tx * 8);
            const float4 p1 = *(const float4*)(Bb + kk * 128 + tx * 8 + 4);
            float bb[8] = {p0.x, p0.y, p0.z, p0.w, p1.x, p1.y, p1.z, p1.w};
            #pragma unroll
            for (int j = 0; j < 8; ++j) {
                C[0][j] += a0 * bb[j];
                C[1][j] += a1 * bb[j];
            }
        }
        buf ^= 1;
    }
}

extern __shared__ float sm[];

__global__ void __launch_bounds__(NT, 1) gcp_kernel(
    const float* __restrict__ node_s, const float* __restrict__ node_v,
    const float* __restrict__ edge_s, const float* __restrict__ edge_v,
    const float* __restrict__ frames,
    const float* __restrict__ g1Wdown, const float* __restrict__ g1Wdf,
    const float* __restrict__ g1Wso,   const float* __restrict__ g1bso,
    const float* __restrict__ g1Wup,   const float* __restrict__ g1Wg,
    const float* __restrict__ g1bg,
    const float* __restrict__ g2Wdown, const float* __restrict__ g2Wdf,
    const float* __restrict__ g2Wso,   const float* __restrict__ g2bso,
    const float* __restrict__ g2Wup,   const float* __restrict__ g2Wg,
    const float* __restrict__ g2bg,
    const float* __restrict__ attW, const float* __restrict__ attb,
    float* __restrict__ out)
{
    const int tid = threadIdx.x;
    const int e0 = blockIdx.x * TILE;
    const int ty = tid >> 4, tx = tid & 15;   // 32 row-groups x 16 col-groups

    float* A    = sm + OFF_A;
    float* VP   = sm + OFF_VP;
    float* VO1  = sm + OFF_VO1;
    float* VH2  = sm + OFF_VH2;
    float* VH   = sm + OFF_VH;
    float* S2   = sm + OFF_S2;
    float* Bs   = sm + OFF_BS;
    float* F    = sm + OFF_F;
    float* VF   = sm + OFF_VF;
    float* GATE = sm + OFF_GATE;
    float* ATTN = sm + OFF_ATTN;
    int*   rows = (int*)(sm + OFF_IDX);
    int*   cols = rows + TILE;
    float* Ws   = sm + OFF_W;

    // ---- load small weights ----
    copyw(Ws + W_DOWN1, g1Wdown, 1296, tid);
    copyw(Ws + W_DF1,   g1Wdf,   108,  tid);
    copyw(Ws + W_UP1,   g1Wup,   576,  tid);
    copyw(Ws + W_G1,    g1Wg,    2048, tid);
    copyw(Ws + W_DOWN2, g2Wdown, 256,  tid);
    copyw(Ws + W_DF2,   g2Wdf,   48,   tid);
    copyw(Ws + W_UP2,   g2Wup,   256,  tid);
    copyw(Ws + W_G2,    g2Wg,    2048, tid);
    copyw(Ws + W_ATT,   attW,    128,  tid);
    copyw(Ws + W_BSO1,  g1bso,   128,  tid);
    copyw(Ws + W_BSO2,  g2bso,   128,  tid);
    copyw(Ws + W_BG1,   g1bg,    16,   tid);
    copyw(Ws + W_BG2,   g2bg,    16,   tid);
    if (tid == 0) Ws[W_ATTB] = attb[0];
    if (tid < TILE) {
        rows[tid] = g_idx[e0 + tid];
        cols[tid] = g_idx[E_TOTAL + e0 + tid];
    }
    __syncthreads();

    // ---- Phase 1: gather ms -> A[:,0:288] (float4), v_pre -> VP (float4), frames -> F ----
    for (int idx = tid; idx < TILE * 72; idx += NT) {
        int e = idx / 72, k4 = idx - e * 72;
        float4 v;
        if (k4 < 32)      v = ((const float4*)node_s)[(size_t)rows[e] * 32 + k4];
        else if (k4 < 40) v = ((const float4*)edge_s)[(size_t)(e0 + e) * 8 + (k4 - 32)];
        else              v = ((const float4*)node_s)[(size_t)cols[e] * 32 + (k4 - 40)];
        float* dst = A + e * ASTR + k4 * 4;   // ASTR odd -> scalar stores
        dst[0] = v.x; dst[1] = v.y; dst[2] = v.z; dst[3] = v.w;
    }
    for (int idx = tid; idx < TILE * 27; idx += NT) {
        int e = idx / 27, k4 = idx - e * 27;
        float4 v;
        if (k4 < 12)      v = ((const float4*)node_v)[(size_t)rows[e] * 12 + k4];
        else if (k4 < 15) v = ((const float4*)edge_v)[(size_t)(e0 + e) * 3 + (k4 - 12)];
        else              v = ((const float4*)node_v)[(size_t)cols[e] * 12 + (k4 - 15)];
        float* dst = VP + e * 108 + k4 * 4;   // VP[e][i*3+d] == v_pre[d][i]
        dst[0] = v.x; dst[1] = v.y; dst[2] = v.z; dst[3] = v.w;
    }
    for (int idx = tid; idx < TILE * 9; idx += NT) {
        int e = idx / 9, r = idx - e * 9;
        F[e * 9 + r] = frames[(size_t)(e0 + e) * 9 + r];
    }
    __syncthreads();

    // ---- Phase 2: v_hid1 [e][d][h] , v_frames1 [e][d][j] ----
    for (int idx = tid; idx < TILE * 108; idx += NT) {
        int e = idx / 108, r = idx - e * 108;
        int d = r / 36, h = r - d * 36;
        float s = 0.f;
        #pragma unroll 4
        for (int i = 0; i < 36; ++i) s += VP[e * 108 + i * 3 + d] * Ws[W_DOWN1 + i * 36 + h];
        VH[e * 108 + d * 36 + h] = s;
    }
    for (int idx = tid; idx < TILE * 9; idx += NT) {
        int e = idx / 9, r = idx - e * 9;
        int d = r / 3, j = r - d * 3;
        float s = 0.f;
        #pragma unroll 4
        for (int i = 0; i < 36; ++i) s += VP[e * 108 + i * 3 + d] * Ws[W_DF1 + i * 3 + j];
        VF[e * 9 + d * 3 + j] = s;
    }
    __syncthreads();

    // ---- Phase 3: v_norm1 -> A[:,288:324], local1 -> A[:,324:333] ----
    for (int idx = tid; idx < TILE * 36; idx += NT) {
        int e = idx / 36, h = idx - e * 36;
        float a = VH[e * 108 + h], b = VH[e * 108 + 36 + h], c = VH[e * 108 + 72 + h];
        A[e * ASTR + 288 + h] = sqrtf(a * a + b * b + c * c + EPS);
    }
    for (int idx = tid; idx < TILE * 9; idx += NT) {
        int e = idx / 9, r = idx - e * 9;
        int j = r / 3, i = r - j * 3;
        float s = 0.f;
        #pragma unroll
        for (int k = 0; k < 3; ++k) s += F[e * 9 + i * 3 + k] * VF[e * 9 + k * 3 + j];
        A[e * ASTR + 324 + r] = s;   // local[j*3+i]
    }
    __syncthreads();

    // ---- Phase 4: GEMM1 (K=333), epilogue silu -> A[:,0:128] ----
    {
        float C[2][8];
        #pragma unroll
        for (int i = 0; i < 2; ++i)
            #pragma unroll
            for (int j = 0; j < 8; ++j) C[i][j] = 0.f;
        gemm_tile(g1Wso, 333, A, Bs, C, ty, tx, tid);
        // last slice reads cols>=320 only; epilogue writes cols 0..127 -> no race
        #pragma unroll
        for (int i = 0; i < 2; ++i) {
            int e = ty * 2 + i;
            #pragma unroll
            for (int j = 0; j < 8; ++j) {
                int o = tx * 8 + j;
                A[e * ASTR + o] = silu(C[i][j] + Ws[W_BSO1 + o]);
            }
        }
    }
    __syncthreads();

    // ---- Phase 5: gate1 = sigmoid(silu(s1) @ Wg1 + bg1) ----
    for (int idx = tid; idx < TILE * 16; idx += NT) {
        int e = idx / 16, o = idx - e * 16;
        float s = Ws[W_BG1 + o];
        #pragma unroll 4
        for (int j = 0; j < 128; ++j) s += A[e * ASTR + j] * Ws[W_G1 + j * 16 + o];
        GATE[e * 16 + o] = sigm(s);
    }
    __syncthreads();

    // ---- Phase 6: v_out1[e][o][d] = gate1 * (v_hid1 @ Wup1) -> VO1 (overwrites VP) ----
    for (int idx = tid; idx < TILE * 48; idx += NT) {
        int e = idx / 48, r = idx - e * 48;
        int o = r / 3, d = r - o * 3;
        float s = 0.f;
        #pragma unroll 4
        for (int h = 0; h < 36; ++h) s += VH[e * 108 + d * 36 + h] * Ws[W_UP1 + h * 16 + o];
        VO1[e * 48 + r] = GATE[e * 16 + o] * s;
    }
    __syncthreads();

    // ---- Phase 7: v_hid2, v_frames2 ----
    for (int idx = tid; idx < TILE * 48; idx += NT) {
        int e = idx / 48, r = idx - e * 48;
        int d = r / 16, h = r - d * 16;
        float s = 0.f;
        #pragma unroll
        for (int o = 0; o < 16; ++o) s += VO1[e * 48 + o * 3 + d] * Ws[W_DOWN2 + o * 16 + h];
        VH2[e * 48 + d * 16 + h] = s;
    }
    for (int idx = tid; idx < TILE * 9; idx += NT) {
        int e = idx / 9, r = idx - e * 9;
        int d = r / 3, j = r - d * 3;
        float s = 0.f;
        #pragma unroll
        for (int o = 0; o < 16; ++o) s += VO1[e * 48 + o * 3 + d] * Ws[W_DF2 + o * 3 + j];
        VF[e * 9 + d * 3 + j] = s;
    }
    __syncthreads();

    // ---- Phase 8: v_norm2 -> A[:,128:144], local2 -> A[:,144:153] ----
    for (int idx = tid; idx < TILE * 16; idx += NT) {
        int e = idx / 16, h = idx - e * 16;
        float a = VH2[e * 48 + h], b = VH2[e * 48 + 16 + h], c = VH2[e * 48 + 32 + h];
        A[e * ASTR + 128 + h] = sqrtf(a * a + b * b + c * c + EPS);
    }
    for (int idx = tid; idx < TILE * 9; idx += NT) {
        int e = idx / 9, r = idx - e * 9;
        int j = r / 3, i = r - j * 3;
        float s = 0.f;
        #pragma unroll
        for (int k = 0; k < 3; ++k) s += F[e * 9 + i * 3 + k] * VF[e * 9 + k * 3 + j];
        A[e * ASTR + 144 + r] = s;
    }
    __syncthreads();

    // ---- Phase 9: GEMM2 (K=153), epilogue silu -> S2 ----
    {
        float C[2][8];
        #pragma unroll
        for (int i = 0; i < 2; ++i)
            #pragma unroll
            for (int j = 0; j < 8; ++j) C[i][j] = 0.f;
        gemm_tile(g2Wso, 153, A, Bs, C, ty, tx, tid);
        #pragma unroll
        for (int i = 0; i < 2; ++i) {
            int e = ty * 2 + i;
            #pragma unroll
            for (int j = 0; j < 8; ++j) {
                int o = tx * 8 + j;
                S2[e * 128 + o] = silu(C[i][j] + Ws[W_BSO2 + o]);
            }
        }
    }
    __syncthreads();

    // ---- Phase 10: gate2 ----
    for (int idx = tid; idx < TILE * 16; idx += NT) {
        int e = idx / 16, o = idx - e * 16;
        float s = Ws[W_BG2 + o];
        #pragma unroll 4
        for (int j = 0; j < 128; ++j) s += S2[e * 128 + j] * Ws[W_G2 + j * 16 + o];
        GATE[e * 16 + o] = sigm(s);
    }
    __syncthreads();

    // ---- Phase 11: v_final (in-place VO1), s_final (in-place A[:,0:128]) ----
    for (int idx = tid; idx < TILE * 48; idx += NT) {
        int e = idx / 48, r = idx - e * 48;
        int o = r / 3, d = r - o * 3;
        float s = 0.f;
        #pragma unroll
        for (int h = 0; h < 16; ++h) s += VH2[e * 48 + d * 16 + h] * Ws[W_UP2 + h * 16 + o];
        VO1[e * 48 + r] += GATE[e * 16 + o] * s;
    }
    for (int idx = tid; idx < TILE * 128; idx += NT) {
        int e = idx >> 7, j = idx & 127;
        A[e * ASTR + j] += S2[e * 128 + j];
    }
    __syncthreads();

    // ---- Phase 12: attention scalar per edge (4 lanes/edge, first 256 threads) ----
    if (tid < 4 * TILE) {
        int e = tid >> 2, l = tid & 3;
        float p = 0.f;
        for (int j = l; j < 128; j += 4) p += A[e * ASTR + j] * Ws[W_ATT + j];
        p += __shfl_down_sync(0xffffffffu, p, 2);
        p += __shfl_down_sync(0xffffffffu, p, 1);
        if (l == 0) ATTN[e] = sigm(p + Ws[W_ATTB]);
    }
    __syncthreads();

    // ---- Phase 13: scatter-add to out[row] ----
    for (int idx = tid; idx < TILE * 128; idx += NT) {
        int e = idx >> 7, j = idx & 127;
        atomicAdd(&out[(size_t)rows[e] * 176 + j], A[e * ASTR + j] * ATTN[e]);
    }
    for (int idx = tid; idx < TILE * 48; idx += NT) {
        int e = idx / 48, r = idx - e * 48;
        atomicAdd(&out[(size_t)rows[e] * 176 + 128 + r], VO1[e * 48 + r]);
    }
}

__global__ void zero_kernel(float4* __restrict__ out, int n4) {
    int i = blockIdx.x * blockDim.x + threadIdx.x;
    if (i < n4) out[i] = make_float4(0.f, 0.f, 0.f, 0.f);
}

extern "C" void kernel_launch(void* const* d_in, const int* in_sizes, int n_in,
                              void* d_out, int out_size) {
    const float* node_s  = (const float*)d_in[0];
    const float* node_v  = (const float*)d_in[1];
    const float* edge_s  = (const float*)d_in[2];
    const float* edge_v  = (const float*)d_in[3];
    const float* frames  = (const float*)d_in[4];
    const float* g1Wdown = (const float*)d_in[5];
    const float* g1Wdf   = (const float*)d_in[6];
    const float* g1Wso   = (const float*)d_in[7];
    const float* g1bso   = (const float*)d_in[8];
    const float* g1Wup   = (const float*)d_in[9];
    const float* g1Wg    = (const float*)d_in[10];
    const float* g1bg    = (const float*)d_in[11];
    const float* g2Wdown = (const float*)d_in[12];
    const float* g2Wdf   = (const float*)d_in[13];
    const float* g2Wso   = (const float*)d_in[14];
    const float* g2bso   = (const float*)d_in[15];
    const float* g2Wup   = (const float*)d_in[16];
    const float* g2Wg    = (const float*)d_in[17];
    const float* g2bg    = (const float*)d_in[18];
    const float* attW    = (const float*)d_in[19];
    const float* attb    = (const float*)d_in[20];
    const int*   ei_raw  = (const int*)d_in[21];   // width detected on device
    float* out = (float*)d_out;

    size_t smem = SMEM_FLOATS * sizeof(float);
    cudaFuncSetAttribute(gcp_kernel, cudaFuncAttributeMaxDynamicSharedMemorySize, (int)smem);

    convert_idx_kernel<<<(2 * E_TOTAL + 255) / 256, 256>>>(ei_raw);

    int n4 = out_size / 4;
    zero_kernel<<<(n4 + 255) / 256, 256>>>((float4*)d_out, n4);

    gcp_kernel<<<E_TOTAL / TILE, NT, smem>>>(
        node_s, node_v, edge_s, edge_v, frames,
        g1Wdown, g1Wdf, g1Wso, g1bso, g1Wup, g1Wg, g1bg,
        g2Wdown, g2Wdf, g2Wso, g2bso, g2Wup, g2Wg, g2bg,
        attW, attb, out);
}

// round 7
// speedup vs baseline: 1.4550x; 1.4550x over previous
#include <cuda_runtime.h>
#include <math.h>

#define E_TOTAL 160000
#define NN 10000
#define TILE 32
#define NT 256
#define ASTR 336   // 333 padded to /4 for float4 k-loads
#define EPS 1e-8f

// ---- dynamic smem layout (float offsets), per CTA ~108KB -> 2 CTAs/SM ----
#define OFF_A     0                      // 32 x 336 = 10752
#define OFF_VP    10752                  // 32 x 108 = 3456 ; reused: VO1(1536)+VH2(1536)
#define OFF_VO1   (OFF_VP)
#define OFF_VH2   (OFF_VP + 1536)
#define OFF_VH    14208                  // 32 x 108 = 3456
#define OFF_S2    17664                  // 32 x 128 = 4096
#define OFF_BS    21760                  // 2 x (16x128) = 4096 (16B aligned)
#define OFF_F     25856                  // 32 x 9 = 288
#define OFF_VF    26144                  // 288
#define OFF_GATE  26432                  // 32 x 16 = 512
#define OFF_ATTN  26944                  // 32
#define OFF_IDX   26976                  // 64 ints
#define SMEM_FLOATS 27040                // 108160 B/CTA; x2 = 216320 B <= 228KB/SM

// normalized edge indices (handles int32-vs-int64 metadata ambiguity)
__device__ int g_idx[2 * E_TOTAL];

__device__ __forceinline__ float sigm(float x) { return 1.0f / (1.0f + __expf(-x)); }
__device__ __forceinline__ float silu(float x) { return x * sigm(x); }

__global__ void convert_idx_kernel(const int* __restrict__ raw) {
    int any = 0;
    #pragma unroll
    for (int i = 1; i < 64; i += 2) any |= raw[i];
    const bool is64 = (any == 0);
    int i = blockIdx.x * blockDim.x + threadIdx.x;
    if (i < 2 * E_TOTAL) g_idx[i] = is64 ? raw[2 * i] : raw[i];
}

// GEMM: C[4][4] += A_tile[32 x K] @ W[K x 128]. A in smem (stride ASTR, /4),
// W streamed through double-buffered Bs (2 x 16 x 128) with register prefetch.
// One barrier per slice (see R5 ordering argument).
__device__ __forceinline__ void gemm_tile(const float* __restrict__ W, int K,
                                          const float* A, float* Bs,
                                          float C[4][4], int ty, int tx, int tid) {
    float4 pre0, pre1;
    {
        int n4 = min(16, K) * 32;
        if (tid < n4)       pre0 = ((const float4*)W)[tid];
        if (tid + NT < n4)  pre1 = ((const float4*)W)[tid + NT];
    }
    int buf = 0;
    for (int k0 = 0; k0 < K; k0 += 16) {
        const int kb = min(16, K - k0);
        const int n4 = kb * 32;
        if (tid < n4)       ((float4*)(Bs + buf * 2048))[tid]      = pre0;
        if (tid + NT < n4)  ((float4*)(Bs + buf * 2048))[tid + NT] = pre1;
        __syncthreads();
        const int k1 = k0 + 16;
        if (k1 < K) {
            const int n41 = min(16, K - k1) * 32;
            const float4* Wn = (const float4*)(W + (size_t)k1 * 128);
            if (tid < n41)      pre0 = Wn[tid];
            if (tid + NT < n41) pre1 = Wn[tid + NT];
        }
        const float* Bb = Bs + buf * 2048;
        const float* Ar = A + (ty * 4) * ASTR + k0;
        int kk = 0;
        for (; kk + 4 <= kb; kk += 4) {
            float4 a0 = *(const float4*)(Ar + 0 * ASTR + kk);
            float4 a1 = *(const float4*)(Ar + 1 * ASTR + kk);
            float4 a2 = *(const float4*)(Ar + 2 * ASTR + kk);
            float4 a3 = *(const float4*)(Ar + 3 * ASTR + kk);
            float aa[4][4] = {{a0.x, a0.y, a0.z, a0.w},
                              {a1.x, a1.y, a1.z, a1.w},
                              {a2.x, a2.y, a2.z, a2.w},
                              {a3.x, a3.y, a3.z, a3.w}};
            #pragma unroll
            for (int j = 0; j < 4; ++j) {
                float4 b = *(const float4*)(Bb + (kk + j) * 128 + tx * 4);
                float bb[4] = {b.x, b.y, b.z, b.w};
                #pragma unroll
                for (int r = 0; r < 4; ++r)
                    #pragma unroll
                    for (int c = 0; c < 4; ++c)
                        C[r][c] += aa[r][j] * bb[c];
            }
        }
        for (; kk < kb; ++kk) {
            float4 b = *(const float4*)(Bb + kk * 128 + tx * 4);
            float bb[4] = {b.x, b.y, b.z, b.w};
            float a0 = Ar[0 * ASTR + kk], a1 = Ar[1 * ASTR + kk];
            float a2 = Ar[2 * ASTR + kk], a3 = Ar[3 * ASTR + kk];
            #pragma unroll
            for (int c = 0; c < 4; ++c) {
                C[0][c] += a0 * bb[c];
                C[1][c] += a1 * bb[c];
                C[2][c] += a2 * bb[c];
                C[3][c] += a3 * bb[c];
            }
        }
        buf ^= 1;
    }
}

extern __shared__ float sm[];

__global__ void __launch_bounds__(NT, 2) gcp_kernel(
    const float* __restrict__ node_s, const float* __restrict__ node_v,
    const float* __restrict__ edge_s, const float* __restrict__ edge_v,
    const float* __restrict__ frames,
    const float* __restrict__ g1Wdown, const float* __restrict__ g1Wdf,
    const float* __restrict__ g1Wso,   const float* __restrict__ g1bso,
    const float* __restrict__ g1Wup,   const float* __restrict__ g1Wg,
    const float* __restrict__ g1bg,
    const float* __restrict__ g2Wdown, const float* __restrict__ g2Wdf,
    const float* __restrict__ g2Wso,   const float* __restrict__ g2bso,
    const float* __restrict__ g2Wup,   const float* __restrict__ g2Wg,
    const float* __restrict__ g2bg,
    const float* __restrict__ attW, const float* __restrict__ attb,
    float* __restrict__ out)
{
    const int tid = threadIdx.x;
    const int e0 = blockIdx.x * TILE;
    const int ty = tid >> 5, tx = tid & 31;   // 8 row-groups x 32 col-groups

    float* A    = sm + OFF_A;
    float* VP   = sm + OFF_VP;
    float* VO1  = sm + OFF_VO1;
    float* VH2  = sm + OFF_VH2;
    float* VH   = sm + OFF_VH;
    float* S2   = sm + OFF_S2;
    float* Bs   = sm + OFF_BS;
    float* F    = sm + OFF_F;
    float* VF   = sm + OFF_VF;
    float* GATE = sm + OFF_GATE;
    float* ATTN = sm + OFF_ATTN;
    int*   rows = (int*)(sm + OFF_IDX);
    int*   cols = rows + TILE;

    if (tid < TILE) {
        rows[tid] = g_idx[e0 + tid];
        cols[tid] = g_idx[E_TOTAL + e0 + tid];
    }
    __syncthreads();

    // ---- Phase 1: gather ms -> A[:,0:288] (float4), v_pre -> VP, frames -> F ----
    for (int idx = tid; idx < TILE * 72; idx += NT) {
        int e = idx / 72, k4 = idx - e * 72;
        float4 v;
        if (k4 < 32)      v = ((const float4*)node_s)[(size_t)rows[e] * 32 + k4];
        else if (k4 < 40) v = ((const float4*)edge_s)[(size_t)(e0 + e) * 8 + (k4 - 32)];
        else              v = ((const float4*)node_s)[(size_t)cols[e] * 32 + (k4 - 40)];
        *(float4*)(A + e * ASTR + k4 * 4) = v;   // ASTR%4==0, k4*4%4==0 -> aligned
    }
    for (int idx = tid; idx < TILE * 27; idx += NT) {
        int e = idx / 27, k4 = idx - e * 27;
        float4 v;
        if (k4 < 12)      v = ((const float4*)node_v)[(size_t)rows[e] * 12 + k4];
        else if (k4 < 15) v = ((const float4*)edge_v)[(size_t)(e0 + e) * 3 + (k4 - 12)];
        else              v = ((const float4*)node_v)[(size_t)cols[e] * 12 + (k4 - 15)];
        float* dst = VP + e * 108 + k4 * 4;   // VP[e][i*3+d] == v_pre[d][i]
        dst[0] = v.x; dst[1] = v.y; dst[2] = v.z; dst[3] = v.w;
    }
    for (int idx = tid; idx < TILE * 9; idx += NT) {
        int e = idx / 9, r = idx - e * 9;
        F[e * 9 + r] = frames[(size_t)(e0 + e) * 9 + r];
    }
    __syncthreads();

    // ---- Phase 2: v_hid1 [e][d][h], v_frames1 [e][d][j] ----
    for (int idx = tid; idx < TILE * 108; idx += NT) {
        int e = idx / 108, r = idx - e * 108;
        int d = r / 36, h = r - d * 36;
        float s = 0.f;
        #pragma unroll 4
        for (int i = 0; i < 36; ++i) s += VP[e * 108 + i * 3 + d] * g1Wdown[i * 36 + h];
        VH[e * 108 + d * 36 + h] = s;
    }
    for (int idx = tid; idx < TILE * 9; idx += NT) {
        int e = idx / 9, r = idx - e * 9;
        int d = r / 3, j = r - d * 3;
        float s = 0.f;
        #pragma unroll 4
        for (int i = 0; i < 36; ++i) s += VP[e * 108 + i * 3 + d] * g1Wdf[i * 3 + j];
        VF[e * 9 + d * 3 + j] = s;
    }
    __syncthreads();

    // ---- Phase 3: v_norm1 -> A[:,288:324], local1 -> A[:,324:333] ----
    for (int idx = tid; idx < TILE * 36; idx += NT) {
        int e = idx / 36, h = idx - e * 36;
        float a = VH[e * 108 + h], b = VH[e * 108 + 36 + h], c = VH[e * 108 + 72 + h];
        A[e * ASTR + 288 + h] = sqrtf(a * a + b * b + c * c + EPS);
    }
    for (int idx = tid; idx < TILE * 9; idx += NT) {
        int e = idx / 9, r = idx - e * 9;
        int j = r / 3, i = r - j * 3;
        float s = 0.f;
        #pragma unroll
        for (int k = 0; k < 3; ++k) s += F[e * 9 + i * 3 + k] * VF[e * 9 + k * 3 + j];
        A[e * ASTR + 324 + r] = s;   // local[j*3+i]
    }
    __syncthreads();

    // ---- Phase 4: GEMM1 (K=333), epilogue silu -> A[:,0:128] ----
    {
        float C[4][4];
        #pragma unroll
        for (int i = 0; i < 4; ++i)
            #pragma unroll
            for (int j = 0; j < 4; ++j) C[i][j] = 0.f;
        gemm_tile(g1Wso, 333, A, Bs, C, ty, tx, tid);
        // last slice reads cols>=320; epilogue writes cols 0..127 -> no race
        #pragma unroll
        for (int i = 0; i < 4; ++i) {
            int e = ty * 4 + i;
            #pragma unroll
            for (int j = 0; j < 4; ++j) {
                int o = tx * 4 + j;
                A[e * ASTR + o] = silu(C[i][j] + g1bso[o]);
            }
        }
    }
    __syncthreads();

    // ---- Phase 5: gate1 = sigmoid(silu(s1) @ Wg1 + bg1) ----
    for (int idx = tid; idx < TILE * 16; idx += NT) {
        int e = idx / 16, o = idx - e * 16;
        float s = g1bg[o];
        #pragma unroll 4
        for (int j = 0; j < 128; ++j) s += A[e * ASTR + j] * g1Wg[j * 16 + o];
        GATE[e * 16 + o] = sigm(s);
    }
    __syncthreads();

    // ---- Phase 6: v_out1[e][o][d] = gate1 * (v_hid1 @ Wup1) -> VO1 (overwrites VP) ----
    for (int idx = tid; idx < TILE * 48; idx += NT) {
        int e = idx / 48, r = idx - e * 48;
        int o = r / 3, d = r - o * 3;
        float s = 0.f;
        #pragma unroll 4
        for (int h = 0; h < 36; ++h) s += VH[e * 108 + d * 36 + h] * g1Wup[h * 16 + o];
        VO1[e * 48 + r] = GATE[e * 16 + o] * s;
    }
    __syncthreads();

    // ---- Phase 7: v_hid2, v_frames2 ----
    for (int idx = tid; idx < TILE * 48; idx += NT) {
        int e = idx / 48, r = idx - e * 48;
        int d = r / 16, h = r - d * 16;
        float s = 0.f;
        #pragma unroll
        for (int o = 0; o < 16; ++o) s += VO1[e * 48 + o * 3 + d] * g2Wdown[o * 16 + h];
        VH2[e * 48 + d * 16 + h] = s;
    }
    for (int idx = tid; idx < TILE * 9; idx += NT) {
        int e = idx / 9, r = idx - e * 9;
        int d = r / 3, j = r - d * 3;
        float s = 0.f;
        #pragma unroll
        for (int o = 0; o < 16; ++o) s += VO1[e * 48 + o * 3 + d] * g2Wdf[o * 3 + j];
        VF[e * 9 + d * 3 + j] = s;
    }
    __syncthreads();

    // ---- Phase 8: v_norm2 -> A[:,128:144], local2 -> A[:,144:153] ----
    for (int idx = tid; idx < TILE * 16; idx += NT) {
        int e = idx / 16, h = idx - e * 16;
        float a = VH2[e * 48 + h], b = VH2[e * 48 + 16 + h], c = VH2[e * 48 + 32 + h];
        A[e * ASTR + 128 + h] = sqrtf(a * a + b * b + c * c + EPS);
    }
    for (int idx = tid; idx < TILE * 9; idx += NT) {
        int e = idx / 9, r = idx - e * 9;
        int j = r / 3, i = r - j * 3;
        float s = 0.f;
        #pragma unroll
        for (int k = 0; k < 3; ++k) s += F[e * 9 + i * 3 + k] * VF[e * 9 + k * 3 + j];
        A[e * ASTR + 144 + r] = s;
    }
    __syncthreads();

    // ---- Phase 9: GEMM2 (K=153), epilogue silu -> S2 ----
    {
        float C[4][4];
        #pragma unroll
        for (int i = 0; i < 4; ++i)
            #pragma unroll
            for (int j = 0; j < 4; ++j) C[i][j] = 0.f;
        gemm_tile(g2Wso, 153, A, Bs, C, ty, tx, tid);
        #pragma unroll
        for (int i = 0; i < 4; ++i) {
            int e = ty * 4 + i;
            #pragma unroll
            for (int j = 0; j < 4; ++j) {
                int o = tx * 4 + j;
                S2[e * 128 + o] = silu(C[i][j] + g2bso[o]);
            }
        }
    }
    __syncthreads();

    // ---- Phase 10: gate2 ----
    for (int idx = tid; idx < TILE * 16; idx += NT) {
        int e = idx / 16, o = idx - e * 16;
        float s = g2bg[o];
        #pragma unroll 4
        for (int j = 0; j < 128; ++j) s += S2[e * 128 + j] * g2Wg[j * 16 + o];
        GATE[e * 16 + o] = sigm(s);
    }
    __syncthreads();

    // ---- Phase 11: v_final (in-place VO1), s_final (in-place A[:,0:128]) ----
    for (int idx = tid; idx < TILE * 48; idx += NT) {
        int e = idx / 48, r = idx - e * 48;
        int o = r / 3, d = r - o * 3;
        float s = 0.f;
        #pragma unroll
        for (int h = 0; h < 16; ++h) s += VH2[e * 48 + d * 16 + h] * g2Wup[h * 16 + o];
        VO1[e * 48 + r] += GATE[e * 16 + o] * s;
    }
    for (int idx = tid; idx < TILE * 128; idx += NT) {
        int e = idx >> 7, j = idx & 127;
        A[e * ASTR + j] += S2[e * 128 + j];
    }
    __syncthreads();

    // ---- Phase 12: attention scalar per edge (4 lanes/edge, first 128 threads) ----
    if (tid < 4 * TILE) {
        int e = tid >> 2, l = tid & 3;
        float p = 0.f;
        for (int j = l; j < 128; j += 4) p += A[e * ASTR + j] * attW[j];
        p += __shfl_down_sync(0xffffffffu, p, 2);
        p += __shfl_down_sync(0xffffffffu, p, 1);
        if (l == 0) ATTN[e] = sigm(p + attb[0]);
    }
    __syncthreads();

    // ---- Phase 13: scatter-add to out[row] ----
    for (int idx = tid; idx < TILE * 128; idx += NT) {
        int e = idx >> 7, j = idx & 127;
        atomicAdd(&out[(size_t)rows[e] * 176 + j], A[e * ASTR + j] * ATTN[e]);
    }
    for (int idx = tid; idx < TILE * 48; idx += NT) {
        int e = idx / 48, r = idx - e * 48;
        atomicAdd(&out[(size_t)rows[e] * 176 + 128 + r], VO1[e * 48 + r]);
    }
}

__global__ void zero_kernel(float4* __restrict__ out, int n4) {
    int i = blockIdx.x * blockDim.x + threadIdx.x;
    if (i < n4) out[i] = make_float4(0.f, 0.f, 0.f, 0.f);
}

extern "C" void kernel_launch(void* const* d_in, const int* in_sizes, int n_in,
                              void* d_out, int out_size) {
    const float* node_s  = (const float*)d_in[0];
    const float* node_v  = (const float*)d_in[1];
    const float* edge_s  = (const float*)d_in[2];
    const float* edge_v  = (const float*)d_in[3];
    const float* frames  = (const float*)d_in[4];
    const float* g1Wdown = (const float*)d_in[5];
    const float* g1Wdf   = (const float*)d_in[6];
    const float* g1Wso   = (const float*)d_in[7];
    const float* g1bso   = (const float*)d_in[8];
    const float* g1Wup   = (const float*)d_in[9];
    const float* g1Wg    = (const float*)d_in[10];
    const float* g1bg    = (const float*)d_in[11];
    const float* g2Wdown = (const float*)d_in[12];
    const float* g2Wdf   = (const float*)d_in[13];
    const float* g2Wso   = (const float*)d_in[14];
    const float* g2bso   = (const float*)d_in[15];
    const float* g2Wup   = (const float*)d_in[16];
    const float* g2Wg    = (const float*)d_in[17];
    const float* g2bg    = (const float*)d_in[18];
    const float* attW    = (const float*)d_in[19];
    const float* attb    = (const float*)d_in[20];
    const int*   ei_raw  = (const int*)d_in[21];   // width detected on device
    float* out = (float*)d_out;

    size_t smem = SMEM_FLOATS * sizeof(float);
    cudaFuncSetAttribute(gcp_kernel, cudaFuncAttributeMaxDynamicSharedMemorySize, (int)smem);

    convert_idx_kernel<<<(2 * E_TOTAL + 255) / 256, 256>>>(ei_raw);

    int n4 = out_size / 4;
    zero_kernel<<<(n4 + 255) / 256, 256>>>((float4*)d_out, n4);

    gcp_kernel<<<E_TOTAL / TILE, NT, smem>>>(
        node_s, node_v, edge_s, edge_v, frames,
        g1Wdown, g1Wdf, g1Wso, g1bso, g1Wup, g1Wg, g1bg,
        g2Wdown, g2Wdf, g2Wso, g2bso, g2Wup, g2Wg, g2bg,
        attW, attb, out);
}

// round 9
// speedup vs baseline: 2.0199x; 1.3883x over previous
#include <cuda_runtime.h>
#include <math.h>

#define E_TOTAL 160000
#define NN 10000
#define TILE 32
#define NT 256
#define EPS 1e-8f
#define ASTR1 80     // GEMM1 panel stride (K=77)
#define ASTR2 160    // GEMM2 panel stride (K=153)

// ---- smem layout (float offsets), ~112KB/CTA -> 2 CTAs/SM ----
#define OFF_A1    0                      // 32 x 80  = 2560
#define OFF_A2    2560                   // 32 x 160 = 5120
#define OFF_SB    7680                   // 32 x 128 = 4096 (P1[row]+P2[col])
#define OFF_VH    11776                  // 32 x 108 = 3456
#define OFF_EV    15232                  // 32 x 12  = 384
#define OFF_F     15616                  // 32 x 9   = 288
#define OFF_S2    (OFF_VH)               // 4096 alias over [VH][EV][F] (dead before S2 writes)
#define OFF_VO1   15904                  // 32 x 48  = 1536
#define OFF_VH2   17440                  // 32 x 48  = 1536
#define OFF_VF    18976                  // 288
#define OFF_GATE  19264                  // 512
#define OFF_ATTN  19776                  // 32
#define OFF_IDX   19808                  // 64 ints
#define OFF_BS    19872                  // 2 x (32x128) = 8192
#define SMEM_FLOATS 28064                // 112256 B/CTA

// ---- device scratch (precomputed per-node partials) ----
__device__ int   g_idx[2 * E_TOTAL];
__device__ float g_P[NN * 256];          // [n][0:128]=node_s@Wso1[0:128]; [128:256]=@Wso1[160:288]
__device__ float g_VdA[NN * 108];        // node_v@Wdown1 rows 0..15   laid out [d][h]
__device__ float g_VdB[NN * 108];        // node_v@Wdown1 rows 20..35
__device__ float g_VfA[NN * 9];          // node_v@Wdf1 rows 0..15     laid out [d][j]
__device__ float g_VfB[NN * 9];          // node_v@Wdf1 rows 20..35

__device__ __forceinline__ float sigm(float x) { return 1.0f / (1.0f + __expf(-x)); }
__device__ __forceinline__ float silu(float x) { return x * sigm(x); }

// ---- pre1: idx convert + out zero + Vd/Vf per-node precompute ----
#define SEG_A (2 * E_TOTAL)
#define SEG_B (NN * 176 / 4)
#define SEG_C (NN * 234)
__global__ void pre1_kernel(const int* __restrict__ raw,
                            const float* __restrict__ node_v,
                            const float* __restrict__ g1Wdown,
                            const float* __restrict__ g1Wdf,
                            float4* __restrict__ out4) {
    int gi = blockIdx.x * blockDim.x + threadIdx.x;
    if (gi < SEG_A) {
        // int64 detection: odd words of little-endian int64 indices < 2^31 are 0
        bool is64 = ((raw[1] | raw[3] | raw[5] | raw[7]) == 0);
        g_idx[gi] = is64 ? raw[2 * gi] : raw[gi];
    } else if (gi < SEG_A + SEG_B) {
        out4[gi - SEG_A] = make_float4(0.f, 0.f, 0.f, 0.f);
    } else if (gi < SEG_A + SEG_B + SEG_C) {
        int t = gi - (SEG_A + SEG_B);
        int n = t / 234, r = t - n * 234;
        const float* nv = node_v + (size_t)n * 48;   // 16 vectors x 3
        if (r < 216) {
            int half = (r >= 108) ? 1 : 0;
            int rr = r - half * 108;
            int d = rr / 36, h = rr - d * 36;
            int ib = half ? 20 : 0;                  // weight-row base only
            float s = 0.f;
            #pragma unroll 4
            for (int i = 0; i < 16; ++i) s += nv[i * 3 + d] * g1Wdown[(ib + i) * 36 + h];
            (half ? g_VdB : g_VdA)[(size_t)n * 108 + rr] = s;
        } else {
            int rr = r - 216;
            int half = (rr >= 9) ? 1 : 0;
            int q = rr - half * 9;
            int d = q / 3, j = q - d * 3;
            int ib = half ? 20 : 0;
            float s = 0.f;
            #pragma unroll 4
            for (int i = 0; i < 16; ++i) s += nv[i * 3 + d] * g1Wdf[(ib + i) * 3 + j];
            (half ? g_VfB : g_VfA)[n * 9 + q] = s;
        }
    }
}

// ---- pre2: P[n][256] = node_s[n] @ [Wso1 rows 0..127 | rows 160..287] ----
__global__ void __launch_bounds__(256) pre2_kernel(const float* __restrict__ node_s,
                                                   const float* __restrict__ g1Wso) {
    __shared__ float As[32 * 128];
    int n0 = blockIdx.x * 32;
    int tid = threadIdx.x;
    for (int i = tid; i < 32 * 32; i += 256) {
        int r = i >> 5, c = i & 31;
        float4 v = (n0 + r < NN) ? ((const float4*)node_s)[(size_t)(n0 + r) * 32 + c]
                                 : make_float4(0.f, 0.f, 0.f, 0.f);
        *(float4*)(As + r * 128 + c * 4) = v;
    }
    __syncthreads();
    int ty = tid >> 5, tx = tid & 31;
    const float* Wb = (tx < 16) ? (g1Wso + tx * 8) : (g1Wso + 160 * 128 + (tx - 16) * 8);
    float C[4][8];
    #pragma unroll
    for (int i = 0; i < 4; ++i)
        #pragma unroll
        for (int j = 0; j < 8; ++j) C[i][j] = 0.f;
    #pragma unroll 4
    for (int k = 0; k < 128; ++k) {
        float4 b0 = *(const float4*)(Wb + (size_t)k * 128);
        float4 b1 = *(const float4*)(Wb + (size_t)k * 128 + 4);
        float bb[8] = {b0.x, b0.y, b0.z, b0.w, b1.x, b1.y, b1.z, b1.w};
        #pragma unroll
        for (int i = 0; i < 4; ++i) {
            float a = As[(ty * 4 + i) * 128 + k];
            #pragma unroll
            for (int j = 0; j < 8; ++j) C[i][j] += a * bb[j];
        }
    }
    int cbase = (tx < 16) ? tx * 8 : 128 + (tx - 16) * 8;
    #pragma unroll
    for (int i = 0; i < 4; ++i) {
        int n = n0 + ty * 4 + i;
        if (n < NN)
            #pragma unroll
            for (int j = 0; j < 8; ++j) g_P[(size_t)n * 256 + cbase + j] = C[i][j];
    }
}

// ---- tile GEMM: C[4][4] += A[32 x K] @ W-slices, 32-k double-buffered ----
template <int NS>
__device__ __forceinline__ void gemm_tile2(const float* __restrict__ W,
                                           const int* kb_arr, const int* base_arr,
                                           const float* A, int astr, float* Bs,
                                           float C[4][4], int w, int l, int tid) {
    float4 pre[4];
    {
        int n4 = kb_arr[0] * 32;
        const float4* src = (const float4*)(W + (size_t)base_arr[0] * 128);
        #pragma unroll
        for (int p = 0; p < 4; ++p) { int i = tid + p * NT; if (i < n4) pre[p] = src[i]; }
    }
    int buf = 0;
    #pragma unroll
    for (int s = 0; s < NS; ++s) {
        const int kb = kb_arr[s];
        {
            int n4 = kb * 32;
            float4* dst = (float4*)(Bs + buf * 4096);
            #pragma unroll
            for (int p = 0; p < 4; ++p) { int i = tid + p * NT; if (i < n4) dst[p * NT + tid] = pre[p]; }
        }
        __syncthreads();
        if (s + 1 < NS) {
            int n41 = kb_arr[s + 1] * 32;
            const float4* src = (const float4*)(W + (size_t)base_arr[s + 1] * 128);
            #pragma unroll
            for (int p = 0; p < 4; ++p) { int i = tid + p * NT; if (i < n41) pre[p] = src[i]; }
        }
        const float* Bb = Bs + buf * 4096;
        const float* Ar = A + (w * 4) * astr + s * 32;
        int kk = 0;
        for (; kk + 4 <= kb; kk += 4) {
            float4 a0 = *(const float4*)(Ar + 0 * astr + kk);
            float4 a1 = *(const float4*)(Ar + 1 * astr + kk);
            float4 a2 = *(const float4*)(Ar + 2 * astr + kk);
            float4 a3 = *(const float4*)(Ar + 3 * astr + kk);
            float aa[4][4] = {{a0.x, a0.y, a0.z, a0.w},
                              {a1.x, a1.y, a1.z, a1.w},
                              {a2.x, a2.y, a2.z, a2.w},
                              {a3.x, a3.y, a3.z, a3.w}};
            #pragma unroll
            for (int j = 0; j < 4; ++j) {
                float4 b = *(const float4*)(Bb + (kk + j) * 128 + l * 4);
                float bb[4] = {b.x, b.y, b.z, b.w};
                #pragma unroll
                for (int r = 0; r < 4; ++r)
                    #pragma unroll
                    for (int c = 0; c < 4; ++c) C[r][c] += aa[r][j] * bb[c];
            }
        }
        for (; kk < kb; ++kk) {
            float4 b = *(const float4*)(Bb + kk * 128 + l * 4);
            float bb[4] = {b.x, b.y, b.z, b.w};
            float a0 = Ar[0 * astr + kk], a1 = Ar[1 * astr + kk];
            float a2 = Ar[2 * astr + kk], a3 = Ar[3 * astr + kk];
            #pragma unroll
            for (int c = 0; c < 4; ++c) {
                C[0][c] += a0 * bb[c];
                C[1][c] += a1 * bb[c];
                C[2][c] += a2 * bb[c];
                C[3][c] += a3 * bb[c];
            }
        }
        buf ^= 1;
    }
}

extern __shared__ float sm[];

__global__ void __launch_bounds__(NT, 2) gcp_kernel(
    const float* __restrict__ edge_s, const float* __restrict__ edge_v,
    const float* __restrict__ frames,
    const float* __restrict__ g1Wdown, const float* __restrict__ g1Wdf,
    const float* __restrict__ g1Wso,   const float* __restrict__ g1bso,
    const float* __restrict__ g1Wup,   const float* __restrict__ g1Wg,
    const float* __restrict__ g1bg,
    const float* __restrict__ g2Wdown, const float* __restrict__ g2Wdf,
    const float* __restrict__ g2Wso,   const float* __restrict__ g2bso,
    const float* __restrict__ g2Wup,   const float* __restrict__ g2Wg,
    const float* __restrict__ g2bg,
    const float* __restrict__ attW, const float* __restrict__ attb,
    float* __restrict__ out)
{
    const int tid = threadIdx.x;
    const int w = tid >> 5, l = tid & 31;   // warp w owns edges 4w..4w+3
    const int e0 = blockIdx.x * TILE;

    float* A1   = sm + OFF_A1;
    float* A2   = sm + OFF_A2;
    float* SB   = sm + OFF_SB;
    float* VH   = sm + OFF_VH;
    float* EV   = sm + OFF_EV;
    float* F    = sm + OFF_F;
    float* S2   = sm + OFF_S2;
    float* VO1  = sm + OFF_VO1;
    float* VH2  = sm + OFF_VH2;
    float* VF   = sm + OFF_VF;
    float* GATE = sm + OFF_GATE;
    float* ATTN = sm + OFF_ATTN;
    int*   rows = (int*)(sm + OFF_IDX);
    int*   cols = rows + TILE;
    float* Bs   = sm + OFF_BS;

    // ---- per-warp gather: indices ----
    if (l < 8) {
        int q = l & 3, e = 4 * w + q;
        int v = g_idx[((l < 4) ? 0 : E_TOTAL) + e0 + e];
        if (l < 4) rows[e] = v; else cols[e] = v;
    }
    __syncwarp();

    // ---- gather: SB = P1[row]+P2[col]; A1 edge_s; EV; F ----
    #pragma unroll
    for (int q = 0; q < 4; ++q) {
        int e = 4 * w + q;
        int row = rows[e], col = cols[e];
        float4 p1 = ((const float4*)g_P)[(size_t)row * 64 + l];
        float4 p2 = ((const float4*)g_P)[(size_t)col * 64 + 32 + l];
        *(float4*)(SB + e * 128 + l * 4) =
            make_float4(p1.x + p2.x, p1.y + p2.y, p1.z + p2.z, p1.w + p2.w);
        if (l < 8)
            *(float4*)(A1 + e * ASTR1 + l * 4) = ((const float4*)edge_s)[(size_t)(e0 + e) * 8 + l];
        else if (l < 11)
            *(float4*)(EV + e * 12 + (l - 8) * 4) = ((const float4*)edge_v)[(size_t)(e0 + e) * 3 + (l - 8)];
        else if (l >= 16 && l < 25)
            F[e * 9 + (l - 16)] = frames[(size_t)(e0 + e) * 9 + (l - 16)];
    }
    __syncwarp();

    // ---- VH = VdA[row]+VdB[col]+edge_v part; VF likewise ----
    #pragma unroll
    for (int q = 0; q < 4; ++q) {
        int e = 4 * w + q;
        int row = rows[e], col = cols[e];
        if (l < 27) {
            float4 a_ = ((const float4*)g_VdA)[(size_t)row * 27 + l];
            float4 b_ = ((const float4*)g_VdB)[(size_t)col * 27 + l];
            float4 acc = make_float4(a_.x + b_.x, a_.y + b_.y, a_.z + b_.z, a_.w + b_.w);
            int d = l / 9, h0 = (l % 9) * 4;
            #pragma unroll
            for (int i = 0; i < 4; ++i) {
                float ev = EV[e * 12 + i * 3 + d];
                float4 wv = *(const float4*)(g1Wdown + (16 + i) * 36 + h0);
                acc.x += ev * wv.x; acc.y += ev * wv.y; acc.z += ev * wv.z; acc.w += ev * wv.w;
            }
            *(float4*)(VH + e * 108 + l * 4) = acc;
        }
    }
    #pragma unroll
    for (int q = 0; q < 4; ++q) {
        int e = 4 * w + q;
        if (l < 9) {
            int row = rows[e], col = cols[e];
            float s = g_VfA[row * 9 + l] + g_VfB[col * 9 + l];
            int d = l / 3, jj = l - d * 3;
            #pragma unroll
            for (int i = 0; i < 4; ++i) s += EV[e * 12 + i * 3 + d] * g1Wdf[(16 + i) * 3 + jj];
            VF[e * 9 + l] = s;
        }
    }
    __syncwarp();

    // ---- vnorm1 -> A1[32:68], local1 -> A1[68:77] ----
    for (int idx = l; idx < 144; idx += 32) {
        int q = idx / 36, h = idx - q * 36, e = 4 * w + q;
        float a = VH[e * 108 + h], b = VH[e * 108 + 36 + h], c = VH[e * 108 + 72 + h];
        A1[e * ASTR1 + 32 + h] = sqrtf(a * a + b * b + c * c + EPS);
    }
    for (int idx = l; idx < 36; idx += 32) {
        int q = idx / 9, r = idx - q * 9, e = 4 * w + q;
        int j = r / 3, i = r - j * 3;
        float s = 0.f;
        #pragma unroll
        for (int k = 0; k < 3; ++k) s += F[e * 9 + i * 3 + k] * VF[e * 9 + k * 3 + j];
        A1[e * ASTR1 + 68 + r] = s;   // local[j*3+i]
    }
    // (no block barrier needed: A1/SB reads in GEMM1+epilogue are warp-local)

    // ---- GEMM1: K=77 (W rows 128..159, 288..319, 320..332), epilogue -> A2[:,0:128] ----
    {
        const int kb1[3]   = {32, 32, 13};
        const int base1[3] = {128, 288, 320};
        float C[4][4];
        #pragma unroll
        for (int i = 0; i < 4; ++i)
            #pragma unroll
            for (int j = 0; j < 4; ++j) C[i][j] = 0.f;
        gemm_tile2<3>(g1Wso, kb1, base1, A1, ASTR1, Bs, C, w, l, tid);
        #pragma unroll
        for (int i = 0; i < 4; ++i) {
            int e = 4 * w + i;
            #pragma unroll
            for (int j = 0; j < 4; ++j) {
                int o = l * 4 + j;
                A2[e * ASTR2 + o] = silu(C[i][j] + SB[e * 128 + o] + g1bso[o]);
            }
        }
    }
    __syncwarp();

    // ---- gate1 ----
    for (int idx = l; idx < 64; idx += 32) {
        int q = idx / 16, o = idx - q * 16, e = 4 * w + q;
        float s = g1bg[o];
        #pragma unroll 4
        for (int j = 0; j < 128; ++j) s += A2[e * ASTR2 + j] * g1Wg[j * 16 + o];
        GATE[e * 16 + o] = sigm(s);
    }
    __syncwarp();

    // ---- vout1 -> VO1 ----
    for (int idx = l; idx < 192; idx += 32) {
        int q = idx / 48, r = idx - q * 48, e = 4 * w + q;
        int o = r / 3, d = r - o * 3;
        float s = 0.f;
        #pragma unroll 4
        for (int h = 0; h < 36; ++h) s += VH[e * 108 + d * 36 + h] * g1Wup[h * 16 + o];
        VO1[e * 48 + r] = GATE[e * 16 + o] * s;
    }
    __syncwarp();

    // ---- vhid2, vf2 ----
    for (int idx = l; idx < 192; idx += 32) {
        int q = idx / 48, r = idx - q * 48, e = 4 * w + q;
        int d = r / 16, h = r - d * 16;
        float s = 0.f;
        #pragma unroll
        for (int o = 0; o < 16; ++o) s += VO1[e * 48 + o * 3 + d] * g2Wdown[o * 16 + h];
        VH2[e * 48 + d * 16 + h] = s;
    }
    for (int idx = l; idx < 36; idx += 32) {
        int q = idx / 9, rr = idx - q * 9, e = 4 * w + q;
        int d = rr / 3, j = rr - d * 3;
        float s = 0.f;
        #pragma unroll
        for (int o = 0; o < 16; ++o) s += VO1[e * 48 + o * 3 + d] * g2Wdf[o * 3 + j];
        VF[e * 9 + rr] = s;
    }
    __syncwarp();

    // ---- vnorm2 -> A2[:,128:144], local2 -> A2[:,144:153] ----
    for (int idx = l; idx < 64; idx += 32) {
        int q = idx / 16, h = idx - q * 16, e = 4 * w + q;
        float a = VH2[e * 48 + h], b = VH2[e * 48 + 16 + h], c = VH2[e * 48 + 32 + h];
        A2[e * ASTR2 + 128 + h] = sqrtf(a * a + b * b + c * c + EPS);
    }
    for (int idx = l; idx < 36; idx += 32) {
        int q = idx / 9, r = idx - q * 9, e = 4 * w + q;
        int j = r / 3, i = r - j * 3;
        float s = 0.f;
        #pragma unroll
        for (int k = 0; k < 3; ++k) s += F[e * 9 + i * 3 + k] * VF[e * 9 + k * 3 + j];
        A2[e * ASTR2 + 144 + r] = s;
    }

    // Bs last read by GEMM1's final slice with no trailing barrier; VH/EV/F
    // (aliased by S2) must be dead in ALL warps before GEMM2 writes S2.
    __syncthreads();

    // ---- GEMM2: K=153, epilogue silu -> S2 ----
    {
        const int kb2[5]   = {32, 32, 32, 32, 25};
        const int base2[5] = {0, 32, 64, 96, 128};
        float C[4][4];
        #pragma unroll
        for (int i = 0; i < 4; ++i)
            #pragma unroll
            for (int j = 0; j < 4; ++j) C[i][j] = 0.f;
        gemm_tile2<5>(g2Wso, kb2, base2, A2, ASTR2, Bs, C, w, l, tid);
        #pragma unroll
        for (int i = 0; i < 4; ++i) {
            int e = 4 * w + i;
            #pragma unroll
            for (int j = 0; j < 4; ++j) {
                int o = l * 4 + j;
                S2[e * 128 + o] = silu(C[i][j] + g2bso[o]);
            }
        }
    }
    __syncwarp();

    // ---- gate2 ----
    for (int idx = l; idx < 64; idx += 32) {
        int q = idx / 16, o = idx - q * 16, e = 4 * w + q;
        float s = g2bg[o];
        #pragma unroll 4
        for (int j = 0; j < 128; ++j) s += S2[e * 128 + j] * g2Wg[j * 16 + o];
        GATE[e * 16 + o] = sigm(s);
    }
    __syncwarp();

    // ---- vfinal (VO1 +=), sfinal (A2 += S2) ----
    for (int idx = l; idx < 192; idx += 32) {
        int q = idx / 48, r = idx - q * 48, e = 4 * w + q;
        int o = r / 3, d = r - o * 3;
        float s = 0.f;
        #pragma unroll
        for (int h = 0; h < 16; ++h) s += VH2[e * 48 + d * 16 + h] * g2Wup[h * 16 + o];
        VO1[e * 48 + r] += GATE[e * 16 + o] * s;
    }
    for (int idx = l; idx < 512; idx += 32) {
        int q = idx >> 7, j = idx & 127, e = 4 * w + q;
        A2[e * ASTR2 + j] += S2[e * 128 + j];
    }
    __syncwarp();

    // ---- attention (8 lanes/edge) ----
    {
        int q = l >> 3, sub = l & 7, e = 4 * w + q;
        float p = 0.f;
        for (int j = sub; j < 128; j += 8) p += A2[e * ASTR2 + j] * attW[j];
        p += __shfl_down_sync(0xffffffffu, p, 4);
        p += __shfl_down_sync(0xffffffffu, p, 2);
        p += __shfl_down_sync(0xffffffffu, p, 1);
        if (sub == 0) ATTN[e] = sigm(p + attb[0]);
    }
    __syncwarp();

    // ---- scatter-add to out[row] ----
    for (int idx = l; idx < 512; idx += 32) {
        int q = idx >> 7, j = idx & 127, e = 4 * w + q;
        atomicAdd(&out[(size_t)rows[e] * 176 + j], A2[e * ASTR2 + j] * ATTN[e]);
    }
    for (int idx = l; idx < 192; idx += 32) {
        int q = idx / 48, r = idx - q * 48, e = 4 * w + q;
        atomicAdd(&out[(size_t)rows[e] * 176 + 128 + r], VO1[e * 48 + r]);
    }
}

extern "C" void kernel_launch(void* const* d_in, const int* in_sizes, int n_in,
                              void* d_out, int out_size) {
    const float* node_s  = (const float*)d_in[0];
    const float* node_v  = (const float*)d_in[1];
    const float* edge_s  = (const float*)d_in[2];
    const float* edge_v  = (const float*)d_in[3];
    const float* frames  = (const float*)d_in[4];
    const float* g1Wdown = (const float*)d_in[5];
    const float* g1Wdf   = (const float*)d_in[6];
    const float* g1Wso   = (const float*)d_in[7];
    const float* g1bso   = (const float*)d_in[8];
    const float* g1Wup   = (const float*)d_in[9];
    const float* g1Wg    = (const float*)d_in[10];
    const float* g1bg    = (const float*)d_in[11];
    const float* g2Wdown = (const float*)d_in[12];
    const float* g2Wdf   = (const float*)d_in[13];
    const float* g2Wso   = (const float*)d_in[14];
    const float* g2bso   = (const float*)d_in[15];
    const float* g2Wup   = (const float*)d_in[16];
    const float* g2Wg    = (const float*)d_in[17];
    const float* g2bg    = (const float*)d_in[18];
    const float* attW    = (const float*)d_in[19];
    const float* attb    = (const float*)d_in[20];
    const int*   ei_raw  = (const int*)d_in[21];
    float* out = (float*)d_out;

    size_t smem = SMEM_FLOATS * sizeof(float);
    cudaFuncSetAttribute(gcp_kernel, cudaFuncAttributeMaxDynamicSharedMemorySize, (int)smem);

    int pre1_total = SEG_A + SEG_B + SEG_C;
    pre1_kernel<<<(pre1_total + 255) / 256, 256>>>(ei_raw, node_v, g1Wdown, g1Wdf, (float4*)d_out);
    pre2_kernel<<<(NN + 31) / 32, 256>>>(node_s, g1Wso);

    gcp_kernel<<<E_TOTAL / TILE, NT, smem>>>(
        edge_s, edge_v, frames,
        g1Wdown, g1Wdf, g1Wso, g1bso, g1Wup, g1Wg, g1bg,
        g2Wdown, g2Wdf, g2Wso, g2bso, g2Wup, g2Wg, g2bg,
        attW, attb, out);
}